// round 10
// baseline (speedup 1.0000x reference)
#include <cuda_runtime.h>
#include <math.h>

typedef unsigned long long ull;

#define DTs   0.2f
#define TILEX 52
#define TILEY 54
#define NTHR  256

// ---- packed f32x2 helpers (sm_103a) ----
__device__ __forceinline__ ull fma2(ull a, ull b, ull c) {
    ull d; asm("fma.rn.f32x2 %0, %1, %2, %3;" : "=l"(d) : "l"(a), "l"(b), "l"(c)); return d;
}
__device__ __forceinline__ ull mul2(ull a, ull b) {
    ull d; asm("mul.rn.f32x2 %0, %1, %2;" : "=l"(d) : "l"(a), "l"(b)); return d;
}
__device__ __forceinline__ ull add2(ull a, ull b) {
    ull d; asm("add.rn.f32x2 %0, %1, %2;" : "=l"(d) : "l"(a), "l"(b)); return d;
}
__device__ __forceinline__ ull pk(float lo, float hi) {
    ull r; asm("mov.b64 %0, {%1, %2};" : "=l"(r) : "f"(lo), "f"(hi)); return r;
}
__device__ __forceinline__ float2 up(ull v) {
    float2 t; asm("mov.b64 {%0, %1}, %2;" : "=f"(t.x), "=f"(t.y) : "l"(v)); return t;
}

struct Line { ull La, Ca, Cb, Rb, Mid; };

// Stencil line from one lane's two pairs a=(c0,c1), b=(c2,c3); edges via
// width-16 shuffles (lane-clamp garbage stays inside the eroded halo).
__device__ __forceinline__ Line make_line(ull a, ull b) {
    const float2 af = up(a), bf = up(b);
    const float el = __shfl_up_sync(0xffffffffu, bf.y, 1, 16);
    const float er = __shfl_down_sync(0xffffffffu, af.x, 1, 16);
    Line L;
    L.La  = pk(el, af.x);
    L.Ca  = a;
    L.Cb  = b;
    L.Mid = pk(af.y, bf.x);
    L.Rb  = pk(bf.y, er);
    return L;
}

struct TrueT  { static constexpr bool value = true;  };
struct FalseT { static constexpr bool value = false; };

__global__ __launch_bounds__(NTHR, 3)
void vib10(const float* __restrict__ force,
           const float* __restrict__ cw,
           const float* __restrict__ omega,
           const float* __restrict__ zeta,
           float* __restrict__ out,
           int H, int W, int C)
{
    __shared__ ulonglong2 bnd[2][34][16];   // boundary rows, double-buffered (+zero guards)
    __shared__ ulonglong2 fs[64][16];       // F*DT^2 pairs

    const int tid  = threadIdx.x;
    const int lane = tid & 31;
    const int l16  = lane & 15;
    const int bi   = ((tid >> 5) << 1) | ((lane >> 4) & 1);  // band 0..15
    const int rb   = bi * 4;

    const int plane = blockIdx.z;
    const int c = plane % C;
    const int bx = blockIdx.x, by = blockIdx.y;
    const bool edge = (bx == 0) | (bx == 4) | (by == 0) | (by == 4);

    const int gx0 = bx * TILEX - 6;
    const int gy0 = by * TILEY - 5;

    // per-channel params
    const float o  = __ldg(omega + c);
    const float zt = __ldg(zeta + c);
    const float w  = log1pf(expf(o));
    const float z  = 1.0f / (1.0f + expf(-zt));
    const float w2 = w * w;
    const float c1 = 1.0f - 2.0f * z * w * DTs;
    const float al = 1.0f + c1 - w2 * DTs * DTs;
    const ull alp  = pk(al, al);
    const ull nc1p = pk(-c1, -c1);

    ull kp[9];
    #pragma unroll
    for (int j = 0; j < 9; j++) {
        const float kv = __ldg(cw + c * 9 + j) * (DTs * DTs);  // fold DT^2
        kp[j] = pk(kv, kv);
    }

    const float* fp = force + (size_t)plane * (H * W);
    const int gc0 = gx0 + l16 * 4;
    const float ca = ((unsigned)gc0 < (unsigned)W) ? 1.0f : 0.0f;
    const float cb = ((unsigned)(gc0 + 2) < (unsigned)W) ? 1.0f : 0.0f;

    // two x generations per row; packed masks (edge path only)
    ull xa[4], xb[4], pa[4], pb[4];
    ull mka[4], mkb[4];

    // ---- init: x1 = F*DT^2, x0 = 0 ----
    #pragma unroll
    for (int i = 0; i < 4; i++) {
        const int gr = gy0 + rb + i;
        float2 fa = make_float2(0.f, 0.f), fb = make_float2(0.f, 0.f);
        if (!edge) {
            fa = *reinterpret_cast<const float2*>(fp + gr * W + gc0);
            fb = *reinterpret_cast<const float2*>(fp + gr * W + gc0 + 2);
        } else {
            const bool rok = (unsigned)gr < (unsigned)H;
            if (rok && ca != 0.0f) fa = *reinterpret_cast<const float2*>(fp + gr * W + gc0);
            if (rok && cb != 0.0f) fb = *reinterpret_cast<const float2*>(fp + gr * W + gc0 + 2);
            const float rm = rok ? 1.0f : 0.0f;
            mka[i] = pk(rm * ca, rm * ca);
            mkb[i] = pk(rm * cb, rm * cb);
        }
        const ull Fa = pk(fa.x * (DTs * DTs), fa.y * (DTs * DTs));
        const ull Fb = pk(fb.x * (DTs * DTs), fb.y * (DTs * DTs));
        ulonglong2 fst; fst.x = Fa; fst.y = Fb;
        fs[rb + i][l16] = fst;
        xa[i] = Fa; xb[i] = Fb;          // x1
        pa[i] = 0ULL; pb[i] = 0ULL;      // x0
    }
    { ulonglong2 p0; p0.x = xa[0]; p0.y = xb[0]; bnd[0][2 * bi + 1][l16] = p0; }
    { ulonglong2 p3; p3.x = xa[3]; p3.y = xb[3]; bnd[0][2 * bi + 2][l16] = p3; }
    if (tid < 16) {
        ulonglong2 zz; zz.x = 0; zz.y = 0;
        bnd[0][0][tid] = zz; bnd[1][0][tid] = zz;
    } else if (tid < 32) {
        ulonglong2 zz; zz.x = 0; zz.y = 0;
        bnd[0][33][tid - 16] = zz; bnd[1][33][tid - 16] = zz;
    }
    __syncthreads();

    // one step: P <- alpha*X - c1*P + (K*DT^2)*X + F*DT^2  [then mask on edge]
    auto step = [&](auto MASKC, ull (&Xa)[4], ull (&Xb)[4],
                    ull (&Pa)[4], ull (&Pb)[4], int sb) {
        constexpr bool MASK = decltype(MASKC)::value;
        ulonglong2 (*cur)[16] = bnd[sb];
        ulonglong2 (*nxt)[16] = bnd[sb ^ 1];

        const ulonglong2 T  = cur[2 * bi][l16];      // row rb-1 (X gen)
        const ulonglong2 Bt = cur[2 * bi + 3][l16];  // row rb+4 (X gen)
        ulonglong2 Fi = fs[rb][l16];
        Line Lt = make_line(T.x, T.y);
        Line Lm = make_line(Xa[0], Xb[0]);

        #pragma unroll
        for (int i = 0; i < 4; i++) {
            const ull ba = (i < 3) ? Xa[i + 1] : Bt.x;
            const ull bb = (i < 3) ? Xb[i + 1] : Bt.y;
            const Line Lb = make_line(ba, bb);
            ulonglong2 Fn = Fi;
            if (i < 3) Fn = fs[rb + i + 1][l16];

            // pair a
            ull a0 = fma2(alp, Xa[i], Fi.x);
            a0 = fma2(nc1p, Pa[i], a0);
            a0 = fma2(kp[0], Lt.La,  a0);
            a0 = fma2(kp[1], Lt.Ca,  a0);
            a0 = fma2(kp[2], Lt.Mid, a0);
            a0 = fma2(kp[3], Lm.La,  a0);
            ull a1 = mul2(kp[4], Xa[i]);
            a1 = fma2(kp[5], Lm.Mid, a1);
            a1 = fma2(kp[7], Lb.Ca,  a1);
            a1 = fma2(kp[6], Lb.La,  a1);
            a1 = fma2(kp[8], Lb.Mid, a1);
            ull ra = add2(a0, a1);
            if (MASK) ra = mul2(ra, mka[i]);
            Pa[i] = ra;

            // pair b
            ull b0 = fma2(alp, Xb[i], Fi.y);
            b0 = fma2(nc1p, Pb[i], b0);
            b0 = fma2(kp[0], Lt.Mid, b0);
            b0 = fma2(kp[1], Lt.Cb,  b0);
            b0 = fma2(kp[2], Lt.Rb,  b0);
            b0 = fma2(kp[3], Lm.Mid, b0);
            ull b1 = mul2(kp[4], Xb[i]);
            b1 = fma2(kp[5], Lm.Rb,  b1);
            b1 = fma2(kp[7], Lb.Cb,  b1);
            b1 = fma2(kp[6], Lb.Mid, b1);
            b1 = fma2(kp[8], Lb.Rb,  b1);
            ull rbv = add2(b0, b1);
            if (MASK) rbv = mul2(rbv, mkb[i]);
            Pb[i] = rbv;

            Lt = Lm; Lm = Lb; Fi = Fn;
        }
        { ulonglong2 p0; p0.x = Pa[0]; p0.y = Pb[0]; nxt[2 * bi + 1][l16] = p0; }
        { ulonglong2 p3; p3.x = Pa[3]; p3.y = Pb[3]; nxt[2 * bi + 2][l16] = p3; }
        __syncthreads();
    };

    // 5 recurrence steps (steps 2..6); parity ping-pongs the generations
    auto mainloop = [&](auto MASKC) {
        #pragma unroll 1
        for (int s = 0; s < 5; s++) {
            if (s & 1) step(MASKC, pa, pb, xa, xb, 1);
            else       step(MASKC, xa, xb, pa, pb, 0);
        }
    };
    if (edge) mainloop(TrueT{});
    else      mainloop(FalseT{});
    // x6 in pa/pb, x5 in xa/xb

    // ---- energy: v6 = (x6-x5)/DT ; E = 0.5 v^2 + 0.5 w2 x6^2 ----
    float* op = out + (size_t)plane * (H * W);
    const ull n1p  = pk(-1.0f, -1.0f);
    const ull qp   = pk(0.5f / (DTs * DTs), 0.5f / (DTs * DTs));
    const ull hw2p = pk(0.5f * w2, 0.5f * w2);
    const bool poka = (l16 >= 2) && (l16 <= 14) && (ca != 0.0f);
    const bool pokb = (l16 >= 1) && (l16 <= 13) && (cb != 0.0f);
    #pragma unroll
    for (int i = 0; i < 4; i++) {
        const int r = rb + i;
        if (r < 5 || r > 58) continue;
        const int gr = gy0 + r;
        if ((unsigned)gr >= (unsigned)H) continue;
        const size_t base = (size_t)gr * W;
        if (poka) {
            const ull d = fma2(n1p, xa[i], pa[i]);           // x6 - x5
            const ull e = fma2(hw2p, mul2(pa[i], pa[i]), mul2(mul2(d, d), qp));
            *reinterpret_cast<ull*>(op + base + gc0) = e;
        }
        if (pokb) {
            const ull d = fma2(n1p, xb[i], pb[i]);
            const ull e = fma2(hw2p, mul2(pb[i], pb[i]), mul2(mul2(d, d), qp));
            *reinterpret_cast<ull*>(op + base + gc0 + 2) = e;
        }
    }
}

extern "C" void kernel_launch(void* const* d_in, const int* in_sizes, int n_in,
                              void* d_out, int out_size)
{
    const float* force = (const float*)d_in[0];
    const float* cw    = (const float*)d_in[1];
    const float* omega = (const float*)d_in[2];
    const float* zeta  = (const float*)d_in[3];
    float* out = (float*)d_out;

    const int H = 256, W = 256;
    const int C = in_sizes[2];
    const int planes = in_sizes[0] / (H * W);

    vib10<<<dim3(5, 5, planes), NTHR>>>(force, cw, omega, zeta, out, H, W, C);
}

// round 11
// speedup vs baseline: 1.2084x; 1.2084x over previous
#include <cuda_runtime.h>
#include <math.h>

typedef unsigned long long ull;

#define DTs   0.2f
#define TILEX 52
#define TILEY 54
#define NTHR  256

// ---- packed f32x2 helpers (sm_103a) ----
__device__ __forceinline__ ull fma2(ull a, ull b, ull c) {
    ull d; asm("fma.rn.f32x2 %0, %1, %2, %3;" : "=l"(d) : "l"(a), "l"(b), "l"(c)); return d;
}
__device__ __forceinline__ ull mul2(ull a, ull b) {
    ull d; asm("mul.rn.f32x2 %0, %1, %2;" : "=l"(d) : "l"(a), "l"(b)); return d;
}
__device__ __forceinline__ ull add2(ull a, ull b) {
    ull d; asm("add.rn.f32x2 %0, %1, %2;" : "=l"(d) : "l"(a), "l"(b)); return d;
}
__device__ __forceinline__ ull pk(float lo, float hi) {
    ull r; asm("mov.b64 %0, {%1, %2};" : "=l"(r) : "f"(lo), "f"(hi)); return r;
}
__device__ __forceinline__ float2 up(ull v) {
    float2 t; asm("mov.b64 {%0, %1}, %2;" : "=f"(t.x), "=f"(t.y) : "l"(v)); return t;
}

struct Line { ull La, Ca, Cb, Rb, Mid; };

// Stencil line from one lane's two pairs a=(c0,c1), b=(c2,c3); edges via
// width-16 shuffles (lane-clamp garbage stays inside the eroded halo).
__device__ __forceinline__ Line make_line(ull a, ull b) {
    const float2 af = up(a), bf = up(b);
    const float el = __shfl_up_sync(0xffffffffu, bf.y, 1, 16);
    const float er = __shfl_down_sync(0xffffffffu, af.x, 1, 16);
    Line L;
    L.La  = pk(el, af.x);
    L.Ca  = a;
    L.Cb  = b;
    L.Mid = pk(af.y, bf.x);
    L.Rb  = pk(bf.y, er);
    return L;
}

__global__ __launch_bounds__(NTHR, 3)
void vib11(const float* __restrict__ force,
           const float* __restrict__ cw,
           const float* __restrict__ omega,
           const float* __restrict__ zeta,
           float* __restrict__ out,
           int H, int W, int C)
{
    __shared__ ulonglong2 bnd[2][34][16];   // boundary rows, double-buffered (+zero guards)
    __shared__ ulonglong2 fs[64][16];       // F*DT^2 pairs

    const int tid  = threadIdx.x;
    const int lane = tid & 31;
    const int l16  = lane & 15;
    const int bi   = ((tid >> 5) << 1) | ((lane >> 4) & 1);  // band 0..15
    const int rb   = bi * 4;

    const int plane = blockIdx.z;
    const int c = plane % C;
    const int bx = blockIdx.x, by = blockIdx.y;

    const int gx0 = bx * TILEX - 6;
    const int gy0 = by * TILEY - 5;

    // per-channel params
    const float o  = __ldg(omega + c);
    const float zt = __ldg(zeta + c);
    const float w  = log1pf(expf(o));
    const float z  = 1.0f / (1.0f + expf(-zt));
    const float w2 = w * w;
    const float c1 = 1.0f - 2.0f * z * w * DTs;
    const float al = 1.0f + c1 - w2 * DTs * DTs;
    const ull alp  = pk(al, al);
    const ull nc1p = pk(-c1, -c1);

    ull kp[9];
    #pragma unroll
    for (int j = 0; j < 9; j++) {
        const float kv = __ldg(cw + c * 9 + j) * (DTs * DTs);  // fold DT^2
        kp[j] = pk(kv, kv);
    }

    const float* fp = force + (size_t)plane * (H * W);
    const int gc0 = gx0 + l16 * 4;
    const float ca = ((unsigned)gc0 < (unsigned)W) ? 1.0f : 0.0f;
    const float cb = ((unsigned)(gc0 + 2) < (unsigned)W) ? 1.0f : 0.0f;

    // two x generations per row-pair; masks PRE-PACKED once (only diff vs round 9)
    ull xa[4], xb[4], pa[4], pb[4];
    ull mka[4], mkb[4];

    // ---- init: x1 = F*DT^2, x0 = 0 ----
    #pragma unroll
    for (int i = 0; i < 4; i++) {
        const int gr = gy0 + rb + i;
        const bool rok = (unsigned)gr < (unsigned)H;
        float2 fa = make_float2(0.f, 0.f), fb = make_float2(0.f, 0.f);
        if (rok && ca != 0.0f) fa = *reinterpret_cast<const float2*>(fp + gr * W + gc0);
        if (rok && cb != 0.0f) fb = *reinterpret_cast<const float2*>(fp + gr * W + gc0 + 2);
        const float rm = rok ? 1.0f : 0.0f;
        mka[i] = pk(rm * ca, rm * ca);
        mkb[i] = pk(rm * cb, rm * cb);
        const ull Fa = pk(fa.x * (DTs * DTs), fa.y * (DTs * DTs));
        const ull Fb = pk(fb.x * (DTs * DTs), fb.y * (DTs * DTs));
        ulonglong2 fst; fst.x = Fa; fst.y = Fb;
        fs[rb + i][l16] = fst;
        xa[i] = Fa; xb[i] = Fb;          // x1
        pa[i] = 0ULL; pb[i] = 0ULL;      // x0
    }
    { ulonglong2 p0; p0.x = xa[0]; p0.y = xb[0]; bnd[0][2 * bi + 1][l16] = p0; }
    { ulonglong2 p3; p3.x = xa[3]; p3.y = xb[3]; bnd[0][2 * bi + 2][l16] = p3; }
    if (tid < 16) {
        ulonglong2 zz; zz.x = 0; zz.y = 0;
        bnd[0][0][tid] = zz; bnd[1][0][tid] = zz;
    } else if (tid < 32) {
        ulonglong2 zz; zz.x = 0; zz.y = 0;
        bnd[0][33][tid - 16] = zz; bnd[1][33][tid - 16] = zz;
    }
    __syncthreads();

    // one step of x-only recurrence: P <- alpha*X - c1*P + (K*DT^2)*X + F*DT^2
    auto step = [&](ull (&Xa)[4], ull (&Xb)[4], ull (&Pa)[4], ull (&Pb)[4], int sb) {
        ulonglong2 (*cur)[16] = bnd[sb];
        ulonglong2 (*nxt)[16] = bnd[sb ^ 1];

        const ulonglong2 T  = cur[2 * bi][l16];      // row rb-1 (X gen)
        const ulonglong2 Bt = cur[2 * bi + 3][l16];  // row rb+4 (X gen)
        ulonglong2 Fi = fs[rb][l16];
        Line Lt = make_line(T.x, T.y);
        Line Lm = make_line(Xa[0], Xb[0]);

        #pragma unroll
        for (int i = 0; i < 4; i++) {
            const ull ba = (i < 3) ? Xa[i + 1] : Bt.x;
            const ull bb = (i < 3) ? Xb[i + 1] : Bt.y;
            const Line Lb = make_line(ba, bb);
            ulonglong2 Fn = Fi;
            if (i < 3) Fn = fs[rb + i + 1][l16];

            // pair a
            ull a0 = fma2(alp, Xa[i], Fi.x);
            a0 = fma2(nc1p, Pa[i], a0);
            a0 = fma2(kp[0], Lt.La,  a0);
            a0 = fma2(kp[1], Lt.Ca,  a0);
            a0 = fma2(kp[2], Lt.Mid, a0);
            a0 = fma2(kp[3], Lm.La,  a0);
            ull a1 = mul2(kp[4], Xa[i]);
            a1 = fma2(kp[5], Lm.Mid, a1);
            a1 = fma2(kp[7], Lb.Ca,  a1);
            a1 = fma2(kp[6], Lb.La,  a1);
            a1 = fma2(kp[8], Lb.Mid, a1);
            Pa[i] = mul2(add2(a0, a1), mka[i]);

            // pair b
            ull b0 = fma2(alp, Xb[i], Fi.y);
            b0 = fma2(nc1p, Pb[i], b0);
            b0 = fma2(kp[0], Lt.Mid, b0);
            b0 = fma2(kp[1], Lt.Cb,  b0);
            b0 = fma2(kp[2], Lt.Rb,  b0);
            b0 = fma2(kp[3], Lm.Mid, b0);
            ull b1 = mul2(kp[4], Xb[i]);
            b1 = fma2(kp[5], Lm.Rb,  b1);
            b1 = fma2(kp[7], Lb.Cb,  b1);
            b1 = fma2(kp[6], Lb.Mid, b1);
            b1 = fma2(kp[8], Lb.Rb,  b1);
            Pb[i] = mul2(add2(b0, b1), mkb[i]);

            Lt = Lm; Lm = Lb; Fi = Fn;
        }
        { ulonglong2 p0; p0.x = Pa[0]; p0.y = Pb[0]; nxt[2 * bi + 1][l16] = p0; }
        { ulonglong2 p3; p3.x = Pa[3]; p3.y = Pb[3]; nxt[2 * bi + 2][l16] = p3; }
        __syncthreads();
    };

    // 5 recurrence steps (steps 2..6); parity ping-pongs the generations
    #pragma unroll 1
    for (int s = 0; s < 5; s++) {
        if (s & 1) step(pa, pb, xa, xb, 1);
        else       step(xa, xb, pa, pb, 0);
    }
    // x6 in pa/pb, x5 in xa/xb

    // ---- energy: v6 = (x6-x5)/DT ; E = 0.5 v^2 + 0.5 w2 x6^2 ----
    float* op = out + (size_t)plane * (H * W);
    const ull n1p  = pk(-1.0f, -1.0f);
    const ull qp   = pk(0.5f / (DTs * DTs), 0.5f / (DTs * DTs));
    const ull hw2p = pk(0.5f * w2, 0.5f * w2);
    const bool poka = (l16 >= 2) && (l16 <= 14) && (ca != 0.0f);
    const bool pokb = (l16 >= 1) && (l16 <= 13) && (cb != 0.0f);
    #pragma unroll
    for (int i = 0; i < 4; i++) {
        const int r = rb + i;
        if (r < 5 || r > 58) continue;
        const int gr = gy0 + r;
        if ((unsigned)gr >= (unsigned)H) continue;
        const size_t base = (size_t)gr * W;
        if (poka) {
            const ull d = fma2(n1p, xa[i], pa[i]);           // x6 - x5
            const ull e = fma2(hw2p, mul2(pa[i], pa[i]), mul2(mul2(d, d), qp));
            *reinterpret_cast<ull*>(op + base + gc0) = e;
        }
        if (pokb) {
            const ull d = fma2(n1p, xb[i], pb[i]);
            const ull e = fma2(hw2p, mul2(pb[i], pb[i]), mul2(mul2(d, d), qp));
            *reinterpret_cast<ull*>(op + base + gc0 + 2) = e;
        }
    }
}

extern "C" void kernel_launch(void* const* d_in, const int* in_sizes, int n_in,
                              void* d_out, int out_size)
{
    const float* force = (const float*)d_in[0];
    const float* cw    = (const float*)d_in[1];
    const float* omega = (const float*)d_in[2];
    const float* zeta  = (const float*)d_in[3];
    float* out = (float*)d_out;

    const int H = 256, W = 256;
    const int C = in_sizes[2];
    const int planes = in_sizes[0] / (H * W);

    vib11<<<dim3(5, 5, planes), NTHR>>>(force, cw, omega, zeta, out, H, W, C);
}

// round 12
// speedup vs baseline: 1.2534x; 1.0372x over previous
#include <cuda_runtime.h>
#include <math.h>

typedef unsigned long long ull;

#define DTs   0.2f
#define TILEX 52
#define TILEY 54
#define NTHR  256

// ---- packed f32x2 helpers (sm_103a) ----
__device__ __forceinline__ ull fma2(ull a, ull b, ull c) {
    ull d; asm("fma.rn.f32x2 %0, %1, %2, %3;" : "=l"(d) : "l"(a), "l"(b), "l"(c)); return d;
}
__device__ __forceinline__ ull mul2(ull a, ull b) {
    ull d; asm("mul.rn.f32x2 %0, %1, %2;" : "=l"(d) : "l"(a), "l"(b)); return d;
}
__device__ __forceinline__ ull add2(ull a, ull b) {
    ull d; asm("add.rn.f32x2 %0, %1, %2;" : "=l"(d) : "l"(a), "l"(b)); return d;
}
__device__ __forceinline__ ull pk(float lo, float hi) {
    ull r; asm("mov.b64 %0, {%1, %2};" : "=l"(r) : "f"(lo), "f"(hi)); return r;
}
__device__ __forceinline__ float2 up(ull v) {
    float2 t; asm("mov.b64 {%0, %1}, %2;" : "=f"(t.x), "=f"(t.y) : "l"(v)); return t;
}

struct Line { ull La, Ca, Cb, Rb, Mid; };

// Stencil line from one lane's two pairs a=(c0,c1), b=(c2,c3); edges via
// width-16 shuffles (lane-clamp garbage stays inside the eroded halo).
__device__ __forceinline__ Line make_line(ull a, ull b) {
    const float2 af = up(a), bf = up(b);
    const float el = __shfl_up_sync(0xffffffffu, bf.y, 1, 16);
    const float er = __shfl_down_sync(0xffffffffu, af.x, 1, 16);
    Line L;
    L.La  = pk(el, af.x);
    L.Ca  = a;
    L.Cb  = b;
    L.Mid = pk(af.y, bf.x);
    L.Rb  = pk(bf.y, er);
    return L;
}

__global__ __launch_bounds__(NTHR, 3)
void vib12(const float* __restrict__ force,
           const float* __restrict__ cw,
           const float* __restrict__ omega,
           const float* __restrict__ zeta,
           float* __restrict__ out,
           int H, int W, int C)
{
    __shared__ ulonglong2 bnd[2][34][16];   // boundary rows, double-buffered (+zero guards)
    __shared__ ulonglong2 fs[64][16];       // F*DT^2 pairs

    const int tid  = threadIdx.x;
    const int lane = tid & 31;
    const int l16  = lane & 15;
    const int bi   = ((tid >> 5) << 1) | ((lane >> 4) & 1);  // band 0..15
    const int rb   = bi * 4;

    const int plane = blockIdx.z;
    const int c = plane % C;
    const int bx = blockIdx.x, by = blockIdx.y;

    const int gx0 = bx * TILEX - 6;
    const int gy0 = by * TILEY - 5;

    // per-channel params
    const float o  = __ldg(omega + c);
    const float zt = __ldg(zeta + c);
    const float w  = log1pf(expf(o));
    const float z  = 1.0f / (1.0f + expf(-zt));
    const float w2 = w * w;
    const float c1 = 1.0f - 2.0f * z * w * DTs;

    // conv taps folded with DT^2; center tap folded into alpha
    float kv[9];
    #pragma unroll
    for (int j = 0; j < 9; j++) kv[j] = __ldg(cw + c * 9 + j) * (DTs * DTs);
    const float al = 1.0f + c1 - w2 * DTs * DTs + kv[4];   // alpha' = alpha + k4*DT^2
    const ull alp  = pk(al, al);
    const ull nc1p = pk(-c1, -c1);
    ull kp0 = pk(kv[0], kv[0]), kp1 = pk(kv[1], kv[1]), kp2 = pk(kv[2], kv[2]);
    ull kp3 = pk(kv[3], kv[3]), kp5 = pk(kv[5], kv[5]);
    ull kp6 = pk(kv[6], kv[6]), kp7 = pk(kv[7], kv[7]), kp8 = pk(kv[8], kv[8]);

    const float* fp = force + (size_t)plane * (H * W);
    const int gc0 = gx0 + l16 * 4;
    const float ca = ((unsigned)gc0 < (unsigned)W) ? 1.0f : 0.0f;
    const float cb = ((unsigned)(gc0 + 2) < (unsigned)W) ? 1.0f : 0.0f;

    // two x generations per row-pair; masks pre-packed once
    ull xa[4], xb[4], pa[4], pb[4];
    ull mka[4], mkb[4];

    // ---- init: x1 = F*DT^2, x0 = 0 ----
    #pragma unroll
    for (int i = 0; i < 4; i++) {
        const int gr = gy0 + rb + i;
        const bool rok = (unsigned)gr < (unsigned)H;
        float2 fa = make_float2(0.f, 0.f), fb = make_float2(0.f, 0.f);
        if (rok && ca != 0.0f) fa = *reinterpret_cast<const float2*>(fp + gr * W + gc0);
        if (rok && cb != 0.0f) fb = *reinterpret_cast<const float2*>(fp + gr * W + gc0 + 2);
        const float rm = rok ? 1.0f : 0.0f;
        mka[i] = pk(rm * ca, rm * ca);
        mkb[i] = pk(rm * cb, rm * cb);
        const ull Fa = pk(fa.x * (DTs * DTs), fa.y * (DTs * DTs));
        const ull Fb = pk(fb.x * (DTs * DTs), fb.y * (DTs * DTs));
        ulonglong2 fst; fst.x = Fa; fst.y = Fb;
        fs[rb + i][l16] = fst;
        xa[i] = Fa; xb[i] = Fb;          // x1
        pa[i] = 0ULL; pb[i] = 0ULL;      // x0
    }
    { ulonglong2 p0; p0.x = xa[0]; p0.y = xb[0]; bnd[0][2 * bi + 1][l16] = p0; }
    { ulonglong2 p3; p3.x = xa[3]; p3.y = xb[3]; bnd[0][2 * bi + 2][l16] = p3; }
    if (tid < 16) {
        ulonglong2 zz; zz.x = 0; zz.y = 0;
        bnd[0][0][tid] = zz; bnd[1][0][tid] = zz;
    } else if (tid < 32) {
        ulonglong2 zz; zz.x = 0; zz.y = 0;
        bnd[0][33][tid - 16] = zz; bnd[1][33][tid - 16] = zz;
    }
    __syncthreads();

    // one step: P <- alpha'*X - c1*P + (K'*DT^2)(off-center taps)*X + F*DT^2
    auto step = [&](ull (&Xa)[4], ull (&Xb)[4], ull (&Pa)[4], ull (&Pb)[4], int sb) {
        ulonglong2 (*cur)[16] = bnd[sb];
        ulonglong2 (*nxt)[16] = bnd[sb ^ 1];

        const ulonglong2 T  = cur[2 * bi][l16];      // row rb-1 (X gen)
        const ulonglong2 Bt = cur[2 * bi + 3][l16];  // row rb+4 (X gen)
        ulonglong2 Fi = fs[rb][l16];
        Line Lt = make_line(T.x, T.y);
        Line Lm = make_line(Xa[0], Xb[0]);

        #pragma unroll
        for (int i = 0; i < 4; i++) {
            const ull ba = (i < 3) ? Xa[i + 1] : Bt.x;
            const ull bb = (i < 3) ? Xb[i + 1] : Bt.y;
            const Line Lb = make_line(ba, bb);
            ulonglong2 Fn = Fi;
            if (i < 3) Fn = fs[rb + i + 1][l16];

            // pair a (center tap folded into alp)
            ull a0 = fma2(alp, Xa[i], Fi.x);
            a0 = fma2(nc1p, Pa[i], a0);
            a0 = fma2(kp0, Lt.La,  a0);
            a0 = fma2(kp1, Lt.Ca,  a0);
            a0 = fma2(kp2, Lt.Mid, a0);
            a0 = fma2(kp3, Lm.La,  a0);
            ull a1 = mul2(kp5, Lm.Mid);
            a1 = fma2(kp7, Lb.Ca,  a1);
            a1 = fma2(kp6, Lb.La,  a1);
            a1 = fma2(kp8, Lb.Mid, a1);
            Pa[i] = mul2(add2(a0, a1), mka[i]);

            // pair b
            ull b0 = fma2(alp, Xb[i], Fi.y);
            b0 = fma2(nc1p, Pb[i], b0);
            b0 = fma2(kp0, Lt.Mid, b0);
            b0 = fma2(kp1, Lt.Cb,  b0);
            b0 = fma2(kp2, Lt.Rb,  b0);
            b0 = fma2(kp3, Lm.Mid, b0);
            ull b1 = mul2(kp5, Lm.Rb);
            b1 = fma2(kp7, Lb.Cb,  b1);
            b1 = fma2(kp6, Lb.Mid, b1);
            b1 = fma2(kp8, Lb.Rb,  b1);
            Pb[i] = mul2(add2(b0, b1), mkb[i]);

            Lt = Lm; Lm = Lb; Fi = Fn;
        }
        { ulonglong2 p0; p0.x = Pa[0]; p0.y = Pb[0]; nxt[2 * bi + 1][l16] = p0; }
        { ulonglong2 p3; p3.x = Pa[3]; p3.y = Pb[3]; nxt[2 * bi + 2][l16] = p3; }
        __syncthreads();
    };

    // 5 recurrence steps (steps 2..6); parity ping-pongs the generations
    #pragma unroll 1
    for (int s = 0; s < 5; s++) {
        if (s & 1) step(pa, pb, xa, xb, 1);
        else       step(xa, xb, pa, pb, 0);
    }
    // x6 in pa/pb, x5 in xa/xb

    // ---- energy: v6 = (x6-x5)/DT ; E = 0.5 v^2 + 0.5 w2 x6^2 ----
    float* op = out + (size_t)plane * (H * W);
    const ull n1p  = pk(-1.0f, -1.0f);
    const ull qp   = pk(0.5f / (DTs * DTs), 0.5f / (DTs * DTs));
    const ull hw2p = pk(0.5f * w2, 0.5f * w2);
    const bool poka = (l16 >= 2) && (l16 <= 14) && (ca != 0.0f);
    const bool pokb = (l16 >= 1) && (l16 <= 13) && (cb != 0.0f);
    #pragma unroll
    for (int i = 0; i < 4; i++) {
        const int r = rb + i;
        if (r < 5 || r > 58) continue;
        const int gr = gy0 + r;
        if ((unsigned)gr >= (unsigned)H) continue;
        const size_t base = (size_t)gr * W;
        if (poka) {
            const ull d = fma2(n1p, xa[i], pa[i]);           // x6 - x5
            const ull e = fma2(hw2p, mul2(pa[i], pa[i]), mul2(mul2(d, d), qp));
            *reinterpret_cast<ull*>(op + base + gc0) = e;
        }
        if (pokb) {
            const ull d = fma2(n1p, xb[i], pb[i]);
            const ull e = fma2(hw2p, mul2(pb[i], pb[i]), mul2(mul2(d, d), qp));
            *reinterpret_cast<ull*>(op + base + gc0 + 2) = e;
        }
    }
}

extern "C" void kernel_launch(void* const* d_in, const int* in_sizes, int n_in,
                              void* d_out, int out_size)
{
    const float* force = (const float*)d_in[0];
    const float* cw    = (const float*)d_in[1];
    const float* omega = (const float*)d_in[2];
    const float* zeta  = (const float*)d_in[3];
    float* out = (float*)d_out;

    const int H = 256, W = 256;
    const int C = in_sizes[2];
    const int planes = in_sizes[0] / (H * W);

    vib12<<<dim3(5, 5, planes), NTHR>>>(force, cw, omega, zeta, out, H, W, C);
}

// round 13
// speedup vs baseline: 1.2841x; 1.0245x over previous
#include <cuda_runtime.h>
#include <math.h>

typedef unsigned long long ull;

#define DTs   0.2f
#define TILEX 52
#define TILEY 54
#define NTHR  256

// ---- packed f32x2 helpers (sm_103a) ----
__device__ __forceinline__ ull fma2(ull a, ull b, ull c) {
    ull d; asm("fma.rn.f32x2 %0, %1, %2, %3;" : "=l"(d) : "l"(a), "l"(b), "l"(c)); return d;
}
__device__ __forceinline__ ull mul2(ull a, ull b) {
    ull d; asm("mul.rn.f32x2 %0, %1, %2;" : "=l"(d) : "l"(a), "l"(b)); return d;
}
__device__ __forceinline__ ull add2(ull a, ull b) {
    ull d; asm("add.rn.f32x2 %0, %1, %2;" : "=l"(d) : "l"(a), "l"(b)); return d;
}
__device__ __forceinline__ ull pk(float lo, float hi) {
    ull r; asm("mov.b64 %0, {%1, %2};" : "=l"(r) : "f"(lo), "f"(hi)); return r;
}
__device__ __forceinline__ float2 up(ull v) {
    float2 t; asm("mov.b64 {%0, %1}, %2;" : "=f"(t.x), "=f"(t.y) : "l"(v)); return t;
}

struct Line { ull La, Ca, Cb, Rb, Mid; };

// Full line build (used for the two step-top lines only).
__device__ __forceinline__ Line make_line(ull a, ull b) {
    const float2 af = up(a), bf = up(b);
    const float el = __shfl_up_sync(0xffffffffu, bf.y, 1, 16);
    const float er = __shfl_down_sync(0xffffffffu, af.x, 1, 16);
    Line L;
    L.La  = pk(el, af.x);
    L.Ca  = a;
    L.Cb  = b;
    L.Mid = pk(af.y, bf.x);
    L.Rb  = pk(bf.y, er);
    return L;
}

// Pack-only line build from prefetched shuffle scalars.
__device__ __forceinline__ Line make_line_pre(ull a, ull b, float el, float er) {
    const float2 af = up(a), bf = up(b);
    Line L;
    L.La  = pk(el, af.x);
    L.Ca  = a;
    L.Cb  = b;
    L.Mid = pk(af.y, bf.x);
    L.Rb  = pk(bf.y, er);
    return L;
}

__global__ __launch_bounds__(NTHR, 3)
void vib13(const float* __restrict__ force,
           const float* __restrict__ cw,
           const float* __restrict__ omega,
           const float* __restrict__ zeta,
           float* __restrict__ out,
           int H, int W, int C)
{
    __shared__ ulonglong2 bnd[2][34][16];   // boundary rows, double-buffered (+zero guards)
    __shared__ ulonglong2 fs[64][16];       // F*DT^2 pairs

    const int tid  = threadIdx.x;
    const int lane = tid & 31;
    const int l16  = lane & 15;
    const int bi   = ((tid >> 5) << 1) | ((lane >> 4) & 1);  // band 0..15
    const int rb   = bi * 4;

    const int plane = blockIdx.z;
    const int c = plane % C;
    const int bx = blockIdx.x, by = blockIdx.y;

    const int gx0 = bx * TILEX - 6;
    const int gy0 = by * TILEY - 5;

    // per-channel params
    const float o  = __ldg(omega + c);
    const float zt = __ldg(zeta + c);
    const float w  = log1pf(expf(o));
    const float z  = 1.0f / (1.0f + expf(-zt));
    const float w2 = w * w;
    const float c1 = 1.0f - 2.0f * z * w * DTs;

    // conv taps folded with DT^2; center tap folded into alpha
    float kv[9];
    #pragma unroll
    for (int j = 0; j < 9; j++) kv[j] = __ldg(cw + c * 9 + j) * (DTs * DTs);
    const float al = 1.0f + c1 - w2 * DTs * DTs + kv[4];
    const ull alp  = pk(al, al);
    const ull nc1p = pk(-c1, -c1);
    ull kp0 = pk(kv[0], kv[0]), kp1 = pk(kv[1], kv[1]), kp2 = pk(kv[2], kv[2]);
    ull kp3 = pk(kv[3], kv[3]), kp5 = pk(kv[5], kv[5]);
    ull kp6 = pk(kv[6], kv[6]), kp7 = pk(kv[7], kv[7]), kp8 = pk(kv[8], kv[8]);

    const float* fp = force + (size_t)plane * (H * W);
    const int gc0 = gx0 + l16 * 4;
    const float ca = ((unsigned)gc0 < (unsigned)W) ? 1.0f : 0.0f;
    const float cb = ((unsigned)(gc0 + 2) < (unsigned)W) ? 1.0f : 0.0f;

    // two x generations per row-pair; masks pre-packed once
    ull xa[4], xb[4], pa[4], pb[4];
    ull mka[4], mkb[4];

    // ---- init: x1 = F*DT^2, x0 = 0 ----
    #pragma unroll
    for (int i = 0; i < 4; i++) {
        const int gr = gy0 + rb + i;
        const bool rok = (unsigned)gr < (unsigned)H;
        float2 fa = make_float2(0.f, 0.f), fb = make_float2(0.f, 0.f);
        if (rok && ca != 0.0f) fa = *reinterpret_cast<const float2*>(fp + gr * W + gc0);
        if (rok && cb != 0.0f) fb = *reinterpret_cast<const float2*>(fp + gr * W + gc0 + 2);
        const float rm = rok ? 1.0f : 0.0f;
        mka[i] = pk(rm * ca, rm * ca);
        mkb[i] = pk(rm * cb, rm * cb);
        const ull Fa = pk(fa.x * (DTs * DTs), fa.y * (DTs * DTs));
        const ull Fb = pk(fb.x * (DTs * DTs), fb.y * (DTs * DTs));
        ulonglong2 fst; fst.x = Fa; fst.y = Fb;
        fs[rb + i][l16] = fst;
        xa[i] = Fa; xb[i] = Fb;          // x1
        pa[i] = 0ULL; pb[i] = 0ULL;      // x0
    }
    { ulonglong2 p0; p0.x = xa[0]; p0.y = xb[0]; bnd[0][2 * bi + 1][l16] = p0; }
    { ulonglong2 p3; p3.x = xa[3]; p3.y = xb[3]; bnd[0][2 * bi + 2][l16] = p3; }
    if (tid < 16) {
        ulonglong2 zz; zz.x = 0; zz.y = 0;
        bnd[0][0][tid] = zz; bnd[1][0][tid] = zz;
    } else if (tid < 32) {
        ulonglong2 zz; zz.x = 0; zz.y = 0;
        bnd[0][33][tid - 16] = zz; bnd[1][33][tid - 16] = zz;
    }
    __syncthreads();

    // one step: P <- alpha'*X - c1*P + off-center conv(X)*DT^2 + F*DT^2
    auto step = [&](ull (&Xa)[4], ull (&Xb)[4], ull (&Pa)[4], ull (&Pb)[4], int sb) {
        ulonglong2 (*cur)[16] = bnd[sb];
        ulonglong2 (*nxt)[16] = bnd[sb ^ 1];

        const ulonglong2 T  = cur[2 * bi][l16];      // row rb-1 (X gen)
        const ulonglong2 Bt = cur[2 * bi + 3][l16];  // row rb+4 (X gen)
        ulonglong2 Fi = fs[rb][l16];
        Line Lt = make_line(T.x, T.y);
        Line Lm = make_line(Xa[0], Xb[0]);

        // prefetch row 0's below-line shuffle scalars
        ull ba = Xa[1], bb = Xb[1];
        float el = __shfl_up_sync(0xffffffffu, up(bb).y, 1, 16);
        float er = __shfl_down_sync(0xffffffffu, up(ba).x, 1, 16);

        #pragma unroll
        for (int i = 0; i < 4; i++) {
            const Line Lb = make_line_pre(ba, bb, el, er);

            // prefetch next row's below-line shuffles + F (hide SHFL/LDS latency)
            ull ba_n = 0, bb_n = 0; float el_n = 0.f, er_n = 0.f;
            ulonglong2 Fn = Fi;
            if (i < 3) {
                ba_n = (i < 2) ? Xa[i + 2] : Bt.x;
                bb_n = (i < 2) ? Xb[i + 2] : Bt.y;
                el_n = __shfl_up_sync(0xffffffffu, up(bb_n).y, 1, 16);
                er_n = __shfl_down_sync(0xffffffffu, up(ba_n).x, 1, 16);
                Fn = fs[rb + i + 1][l16];
            }

            // pair a (center tap folded into alp)
            ull a0 = fma2(alp, Xa[i], Fi.x);
            a0 = fma2(nc1p, Pa[i], a0);
            a0 = fma2(kp0, Lt.La,  a0);
            a0 = fma2(kp1, Lt.Ca,  a0);
            a0 = fma2(kp2, Lt.Mid, a0);
            a0 = fma2(kp3, Lm.La,  a0);
            ull a1 = mul2(kp5, Lm.Mid);
            a1 = fma2(kp7, Lb.Ca,  a1);
            a1 = fma2(kp6, Lb.La,  a1);
            a1 = fma2(kp8, Lb.Mid, a1);
            Pa[i] = mul2(add2(a0, a1), mka[i]);

            // pair b
            ull b0 = fma2(alp, Xb[i], Fi.y);
            b0 = fma2(nc1p, Pb[i], b0);
            b0 = fma2(kp0, Lt.Mid, b0);
            b0 = fma2(kp1, Lt.Cb,  b0);
            b0 = fma2(kp2, Lt.Rb,  b0);
            b0 = fma2(kp3, Lm.Mid, b0);
            ull b1 = mul2(kp5, Lm.Rb);
            b1 = fma2(kp7, Lb.Cb,  b1);
            b1 = fma2(kp6, Lb.Mid, b1);
            b1 = fma2(kp8, Lb.Rb,  b1);
            Pb[i] = mul2(add2(b0, b1), mkb[i]);

            Lt = Lm; Lm = Lb;
            ba = ba_n; bb = bb_n; el = el_n; er = er_n; Fi = Fn;
        }
        { ulonglong2 p0; p0.x = Pa[0]; p0.y = Pb[0]; nxt[2 * bi + 1][l16] = p0; }
        { ulonglong2 p3; p3.x = Pa[3]; p3.y = Pb[3]; nxt[2 * bi + 2][l16] = p3; }
        __syncthreads();
    };

    // 5 recurrence steps (steps 2..6); parity ping-pongs the generations
    #pragma unroll 1
    for (int s = 0; s < 5; s++) {
        if (s & 1) step(pa, pb, xa, xb, 1);
        else       step(xa, xb, pa, pb, 0);
    }
    // x6 in pa/pb, x5 in xa/xb

    // ---- energy: v6 = (x6-x5)/DT ; E = 0.5 v^2 + 0.5 w2 x6^2 ----
    float* op = out + (size_t)plane * (H * W);
    const ull n1p  = pk(-1.0f, -1.0f);
    const ull qp   = pk(0.5f / (DTs * DTs), 0.5f / (DTs * DTs));
    const ull hw2p = pk(0.5f * w2, 0.5f * w2);
    const bool poka = (l16 >= 2) && (l16 <= 14) && (ca != 0.0f);
    const bool pokb = (l16 >= 1) && (l16 <= 13) && (cb != 0.0f);
    #pragma unroll
    for (int i = 0; i < 4; i++) {
        const int r = rb + i;
        if (r < 5 || r > 58) continue;
        const int gr = gy0 + r;
        if ((unsigned)gr >= (unsigned)H) continue;
        const size_t base = (size_t)gr * W;
        if (poka) {
            const ull d = fma2(n1p, xa[i], pa[i]);           // x6 - x5
            const ull e = fma2(hw2p, mul2(pa[i], pa[i]), mul2(mul2(d, d), qp));
            *reinterpret_cast<ull*>(op + base + gc0) = e;
        }
        if (pokb) {
            const ull d = fma2(n1p, xb[i], pb[i]);
            const ull e = fma2(hw2p, mul2(pb[i], pb[i]), mul2(mul2(d, d), qp));
            *reinterpret_cast<ull*>(op + base + gc0 + 2) = e;
        }
    }
}

extern "C" void kernel_launch(void* const* d_in, const int* in_sizes, int n_in,
                              void* d_out, int out_size)
{
    const float* force = (const float*)d_in[0];
    const float* cw    = (const float*)d_in[1];
    const float* omega = (const float*)d_in[2];
    const float* zeta  = (const float*)d_in[3];
    float* out = (float*)d_out;

    const int H = 256, W = 256;
    const int C = in_sizes[2];
    const int planes = in_sizes[0] / (H * W);

    vib13<<<dim3(5, 5, planes), NTHR>>>(force, cw, omega, zeta, out, H, W, C);
}